// round 5
// baseline (speedup 1.0000x reference)
#include <cuda_runtime.h>
#include <math.h>

#define BATCH 16
#define NCLS 90
#define NANCH 9
#define KSEL 5000
#define NSLOT 5120
#define NCHUNK 160
#define NDET 100
#define CAND_CAP 131072
#define STAGE_CAP 2048
#define S_TARGET 384
#define NS_TOTAL 17264

typedef unsigned long long u64;
typedef unsigned int u32;

// ---------------- device scratch (static, no runtime alloc) ----------------
__device__ u32   g_hist[BATCH][2048];
__device__ float g_thr[BATCH];
__device__ int   g_cand_cnt[BATCH];
__device__ float g_cand_val[BATCH][CAND_CAP];
__device__ int   g_cand_idx[BATCH][CAND_CAP];
__device__ float4 g_nms_box[BATCH][NSLOT];
__device__ float  g_nms_score[BATCH][NSLOT];
__device__ int    g_nms_cls[BATCH][NSLOT];
__device__ u32    g_nms_org[BATCH][NSLOT];
__device__ u32    g_nms_fidx[BATCH][NSLOT];

__device__ __forceinline__ u32 fkey(float f) {
    u32 u = __float_as_uint(f);
    return u ^ ((u32)((int)u >> 31) | 0x80000000u);   // monotonic: f1<f2 <=> key1<key2
}
__device__ __forceinline__ float ikey(u32 k) {
    u32 u = (k & 0x80000000u) ? (k ^ 0x80000000u) : ~k;
    return __uint_as_float(u);
}

// ---------------- kernel 0: zero counters/hist ----------------
__global__ void k_zero() {
    int t = blockIdx.x * blockDim.x + threadIdx.x;
    if (t < BATCH * 2048) ((u32*)g_hist)[t] = 0;
    if (t < BATCH) g_cand_cnt[t] = 0;
}

// ---------------- kernel 1: sampled histogram (1/64), all levels, one launch ----------------
__global__ void k_sample(const float* __restrict__ c0, const float* __restrict__ c1,
                         const float* __restrict__ c2, const float* __restrict__ c3,
                         const float* __restrict__ c4) {
    int t = blockIdx.x * blockDim.x + threadIdx.x;
    if (t >= BATCH * NS_TOTAL) return;
    int b = t / NS_TOTAL;
    int r = t - b * NS_TOTAL;
    const float* cls; int chw, i;
    if (r < 12960)      { cls = c0; chw = 3317760; i = r; }
    else if (r < 16200) { cls = c1; chw = 829440;  i = r - 12960; }
    else if (r < 17010) { cls = c2; chw = 207360;  i = r - 16200; }
    else if (r < 17213) { cls = c3; chw = 51840;   i = r - 17010; }
    else                { cls = c4; chw = 12960;   i = r - 17213; }
    int off = i * 256;
    if (off + 4 > chw) return;
    float4 v = __ldg((const float4*)(cls + (long)b * chw + off));
    atomicAdd(&g_hist[b][fkey(v.x) >> 21], 1u);
    atomicAdd(&g_hist[b][fkey(v.y) >> 21], 1u);
    atomicAdd(&g_hist[b][fkey(v.z) >> 21], 1u);
    atomicAdd(&g_hist[b][fkey(v.w) >> 21], 1u);
}

// ---------------- kernel 2: per-image threshold from sample hist ----------------
__global__ void k_thresh() {
    int b = threadIdx.x;
    if (b >= BATCH) return;
    u32 cum = 0;
    int bin = 2047;
    for (; bin >= 0; --bin) {
        cum += g_hist[b][bin];
        if (cum >= S_TARGET) break;
    }
    if (bin < 0) bin = 0;
    u32 kthr = ((u32)bin) << 21;
    u32 u = (kthr & 0x80000000u) ? (kthr ^ 0x80000000u) : ~kthr;
    g_thr[b] = __uint_as_float(u);
}

// ---------------- kernel 3: full scan + compaction, all levels, one launch ----------------
__global__ void k_compact(const float* __restrict__ c0, const float* __restrict__ c1,
                          const float* __restrict__ c2, const float* __restrict__ c3,
                          const float* __restrict__ c4) {
    __shared__ float s_val[STAGE_CAP];
    __shared__ int   s_idx[STAGE_CAP];
    __shared__ int   s_cnt, s_base;
    int b = blockIdx.y;
    int tid = threadIdx.x;
    int blk = blockIdx.x;
    const float* cls; int chw4, shHW, aoff, lb;
    if (blk < 405)      { cls = c0; chw4 = 829440; shHW = 12; aoff = 0;     lb = blk; }
    else if (blk < 507) { cls = c1; chw4 = 207360; shHW = 10; aoff = 36864; lb = blk - 405; }
    else if (blk < 533) { cls = c2; chw4 = 51840;  shHW = 8;  aoff = 46080; lb = blk - 507; }
    else if (blk < 540) { cls = c3; chw4 = 12960;  shHW = 6;  aoff = 48384; lb = blk - 533; }
    else                { cls = c4; chw4 = 3240;   shHW = 4;  aoff = 48960; lb = blk - 540; }

    if (tid == 0) s_cnt = 0;
    __syncthreads();
    float thr = g_thr[b];
    const float4* base = (const float4*)cls + (long)b * chw4;
    int i0 = lb * 2048 + tid;

    float4 v[8];
    #pragma unroll
    for (int g = 0; g < 8; g++) {
        int i4 = i0 + g * 256;
        v[g] = (i4 < chw4) ? __ldg(base + i4)
                           : make_float4(-INFINITY, -INFINITY, -INFINITY, -INFINITY);
    }
    #pragma unroll
    for (int g = 0; g < 8; g++) {
        int i4 = i0 + g * 256;
        #pragma unroll
        for (int j = 0; j < 4; j++) {
            float f = (j == 0) ? v[g].x : (j == 1) ? v[g].y : (j == 2) ? v[g].z : v[g].w;
            if (f >= thr) {
                int lin = i4 * 4 + j;
                int ch = lin >> shHW;                 // 0..809 (= a*90 + c)
                int pix = lin & ((1 << shHW) - 1);    // h*W + w
                int a = ch / NCLS;
                int c = ch - a * NCLS;
                int flat = (aoff + pix * NANCH + a) * NCLS + c;
                int p = atomicAdd(&s_cnt, 1);
                if (p < STAGE_CAP) { s_val[p] = f; s_idx[p] = flat; }
            }
        }
    }
    __syncthreads();
    if (tid == 0) {
        int n = min(s_cnt, STAGE_CAP);
        s_base = atomicAdd(&g_cand_cnt[b], n);
        s_cnt = n;
    }
    __syncthreads();
    for (int i = tid; i < s_cnt; i += 256) {
        int gi = s_base + i;
        if (gi < CAND_CAP) {
            g_cand_val[b][gi] = s_val[i];
            g_cand_idx[b][gi] = s_idx[i];
        }
    }
}

// ---------------- decode helper (fused into select) ----------------
__device__ __forceinline__ void decode_store(
    int b, int slot, float v, int flat,
    const float* __restrict__ b0, const float* __restrict__ b1,
    const float* __restrict__ b2, const float* __restrict__ b3,
    const float* __restrict__ b4, const float* __restrict__ anchors)
{
    int anchor = flat / NCLS;
    int cls = flat - anchor * NCLS;

    const float* bp; int hw, loc;
    if (anchor < 36864)      { bp = b0; hw = 4096; loc = anchor; }
    else if (anchor < 46080) { bp = b1; hw = 1024; loc = anchor - 36864; }
    else if (anchor < 48384) { bp = b2; hw = 256;  loc = anchor - 46080; }
    else if (anchor < 48960) { bp = b3; hw = 64;   loc = anchor - 48384; }
    else                     { bp = b4; hw = 16;   loc = anchor - 48960; }
    int a = loc % NANCH;
    int pix = loc / NANCH;

    const float* q = bp + ((long)b * 36 + a * 4) * hw + pix;
    float ty = __ldg(q);
    float tx = __ldg(q + hw);
    float th = __ldg(q + 2 * hw);
    float tw = __ldg(q + 3 * hw);

    float4 anc = __ldg((const float4*)(anchors + 4 * anchor)); // y1,x1,y2,x2
    float ya = (anc.x + anc.z) * 0.5f;
    float xa = (anc.y + anc.w) * 0.5f;
    float ha = anc.z - anc.x;
    float wa = anc.w - anc.y;
    float w = expf(tw) * wa;
    float h = expf(th) * ha;
    float yc = ty * ha + ya;
    float xc = tx * wa + xa;

    g_nms_box[b][slot] = make_float4(xc - w * 0.5f, yc - h * 0.5f,
                                     xc + w * 0.5f, yc + h * 0.5f);
    g_nms_score[b][slot] = __fdiv_rn(1.0f, 1.0f + expf(-v));
    g_nms_cls[b][slot] = cls;
    g_nms_org[b][slot] = fkey(v);
    g_nms_fidx[b][slot] = (u32)flat;
}

// ---------------- kernel 4: exact top-K select (unordered) + fused decode ----------------
__global__ void __launch_bounds__(1024, 1) k_select(
    const float* __restrict__ b0, const float* __restrict__ b1,
    const float* __restrict__ b2, const float* __restrict__ b3,
    const float* __restrict__ b4, const float* __restrict__ anchors)
{
    __shared__ u32 hist[4096];
    __shared__ u32 s_part[1024];
    __shared__ int sb_bin, sb_above;
    __shared__ int s_tie_cnt, s_out_cnt;
    __shared__ u32 s_tie_key[1024];
    __shared__ int s_tie_idx[1024];
    __shared__ unsigned char s_tie_sel[1024];

    int b = blockIdx.x;
    int tid = threadIdx.x;
    int m = min(g_cand_cnt[b], CAND_CAP);

    // ---- round 1: histogram of top 12 key bits ----
    for (int i = tid; i < 4096; i += 1024) hist[i] = 0;
    if (tid == 0) { s_tie_cnt = 0; s_out_cnt = 0; sb_bin = -1; }
    __syncthreads();
    for (int i = tid; i < m; i += 1024)
        atomicAdd(&hist[fkey(g_cand_val[b][i]) >> 20], 1u);
    __syncthreads();

    // parallel suffix-sum bin search: largest bin with suffix(bin) >= KSEL
    {
        u32 loc = hist[4 * tid] + hist[4 * tid + 1] + hist[4 * tid + 2] + hist[4 * tid + 3];
        s_part[tid] = loc;
        __syncthreads();
        for (int off = 1; off < 1024; off <<= 1) {
            u32 v = s_part[tid];
            u32 add = (tid + off < 1024) ? s_part[tid + off] : 0;
            __syncthreads();
            s_part[tid] = v + add;
            __syncthreads();
        }
        u32 running = (tid < 1023) ? s_part[tid + 1] : 0;
        #pragma unroll
        for (int bb = 3; bb >= 0; --bb) {
            u32 c = hist[4 * tid + bb];
            if (running < (u32)KSEL && running + c >= (u32)KSEL) {
                sb_bin = 4 * tid + bb;
                sb_above = (int)running;
            }
            running += c;
        }
    }
    __syncthreads();
    if (tid == 0 && sb_bin < 0) { sb_bin = 0; sb_above = (int)s_part[0]; }
    __syncthreads();
    int B1 = sb_bin;
    int cntAbove = sb_above;
    __syncthreads();

    // ---- round 2: next 12 bits within bin B1 ----
    for (int i = tid; i < 4096; i += 1024) hist[i] = 0;
    if (tid == 0) sb_bin = -1;
    __syncthreads();
    for (int i = tid; i < m; i += 1024) {
        u32 k = fkey(g_cand_val[b][i]);
        if ((int)(k >> 20) == B1) atomicAdd(&hist[(k >> 8) & 0xFFF], 1u);
    }
    __syncthreads();
    int K2 = KSEL - cntAbove;   // >= 1
    {
        u32 loc = hist[4 * tid] + hist[4 * tid + 1] + hist[4 * tid + 2] + hist[4 * tid + 3];
        s_part[tid] = loc;
        __syncthreads();
        for (int off = 1; off < 1024; off <<= 1) {
            u32 v = s_part[tid];
            u32 add = (tid + off < 1024) ? s_part[tid + off] : 0;
            __syncthreads();
            s_part[tid] = v + add;
            __syncthreads();
        }
        u32 running = (tid < 1023) ? s_part[tid + 1] : 0;
        #pragma unroll
        for (int bb = 3; bb >= 0; --bb) {
            u32 c = hist[4 * tid + bb];
            if (running < (u32)K2 && running + c >= (u32)K2) {
                sb_bin = 4 * tid + bb;
                sb_above = (int)running;
            }
            running += c;
        }
    }
    __syncthreads();
    if (tid == 0 && sb_bin < 0) { sb_bin = 0; sb_above = 0; }
    __syncthreads();
    u32 P = (((u32)B1) << 12) | (u32)sb_bin;
    int need2 = K2 - sb_above;
    __syncthreads();

    // ---- round 3: exact ranking of tie bucket (value desc, flat idx asc) ----
    for (int i = tid; i < m; i += 1024) {
        u32 k = fkey(g_cand_val[b][i]);
        if ((k >> 8) == P) {
            int p = atomicAdd(&s_tie_cnt, 1);
            if (p < 1024) { s_tie_key[p] = k; s_tie_idx[p] = g_cand_idx[b][i]; }
        }
    }
    __syncthreads();
    int ne = min(s_tie_cnt, 1024);
    for (int j = tid; j < ne; j += 1024) {
        u32 kj = s_tie_key[j]; int ij = s_tie_idx[j]; int r = 0;
        for (int i = 0; i < ne; i++) {
            u32 ki = s_tie_key[i];
            if (ki > kj || (ki == kj && s_tie_idx[i] < ij)) r++;
        }
        s_tie_sel[j] = (r < need2) ? 1 : 0;
    }
    __syncthreads();

    // emit exact top-K (unordered) with fused decode
    for (int i = tid; i < m; i += 1024) {
        float v = g_cand_val[b][i];
        u32 k = fkey(v);
        if ((k >> 8) > P) {
            int p = atomicAdd(&s_out_cnt, 1);
            if (p < KSEL) decode_store(b, p, v, g_cand_idx[b][i], b0, b1, b2, b3, b4, anchors);
        }
    }
    __syncthreads();
    for (int j = tid; j < ne; j += 1024) {
        if (s_tie_sel[j]) {
            int p = atomicAdd(&s_out_cnt, 1);
            if (p < KSEL) decode_store(b, p, ikey(s_tie_key[j]), s_tie_idx[j], b0, b1, b2, b3, b4, anchors);
        }
    }
    __syncthreads();
    int cnt = min(s_out_cnt, KSEL);
    // padding slots
    for (int k = cnt + tid; k < NSLOT; k += 1024) {
        g_nms_box[b][k] = make_float4(0.f, 0.f, 0.f, 0.f);
        g_nms_score[b][k] = -INFINITY;
        g_nms_cls[b][k] = 0;
        g_nms_org[b][k] = 0u;
        g_nms_fidx[b][k] = 0xFFFFFFFFu;
    }
}

// ---------------- kernel 5: lazy gaussian soft-NMS, 1 CTA per image ----------------
__device__ __forceinline__ void wredmax128(u64& hi, u64& lo) {
    #pragma unroll
    for (int off = 16; off > 0; off >>= 1) {
        u64 ohi = __shfl_xor_sync(0xFFFFFFFFu, hi, off);
        u64 olo = __shfl_xor_sync(0xFFFFFFFFu, lo, off);
        if (ohi > hi || (ohi == hi && olo > lo)) { hi = ohi; lo = olo; }
    }
}

extern __shared__ unsigned char nms_dyn[];
__global__ void __launch_bounds__(1024, 1) k_nms(float* __restrict__ out) {
    float4* sbox   = (float4*)nms_dyn;                       // NSLOT * 16
    u64*    s_hi   = (u64*)(sbox + NSLOT);                   // NSLOT * 8
    u64*    s_lo   = (u64*)(s_hi + NSLOT);                   // NSLOT * 8
    u32*    s_upd  = (u32*)(s_lo + NSLOT);                   // NSLOT * 4
    float4* selbox = (float4*)(s_upd + NSLOT);               // NDET * 16

    __shared__ u64 s_chi[NCHUNK], s_clo[NCHUNK];
    __shared__ u64 s_whi[5], s_wlo[5];
    __shared__ u64 s_bhi, s_blo;

    int b = blockIdx.x;
    int tid = threadIdx.x;
    int lane = tid & 31;
    int wid = tid >> 5;

    // init slot state
    for (int s = tid; s < NSLOT; s += 1024) {
        sbox[s] = g_nms_box[b][s];
        float sc = g_nms_score[b][s];
        s_hi[s] = (((u64)fkey(sc)) << 32) | g_nms_org[b][s];
        u32 fidx = g_nms_fidx[b][s];
        s_lo[s] = (((u64)(~fidx)) << 32) | (((u32)g_nms_cls[b][s]) << 16) | (u32)s;
        s_upd[s] = 0;
    }
    __syncthreads();
    // build chunk maxima: warp w handles chunks w, w+32, w+64, w+96, w+128
    #pragma unroll
    for (int cc = 0; cc < 5; cc++) {
        int c = wid + cc * 32;
        u64 hi = s_hi[c * 32 + lane];
        u64 lo = s_lo[c * 32 + lane];
        wredmax128(hi, lo);
        if (lane == 0) { s_chi[c] = hi; s_clo[c] = lo; }
    }
    __syncthreads();

    float* o = out + b * (NDET * 6);
    int t = 0;
    while (t < NDET) {
        // hierarchical argmax over 160 chunk maxima
        if (tid < NCHUNK) {
            u64 hi = s_chi[tid], lo = s_clo[tid];
            wredmax128(hi, lo);
            if (lane == 0) { s_whi[wid] = hi; s_wlo[wid] = lo; }
        }
        __syncthreads();
        if (tid == 0) {
            u64 hi = s_whi[0], lo = s_wlo[0];
            #pragma unroll
            for (int i = 1; i < 5; i++) {
                u64 ohi = s_whi[i], olo = s_wlo[i];
                if (ohi > hi || (ohi == hi && olo > lo)) { hi = ohi; lo = olo; }
            }
            s_bhi = hi; s_blo = lo;
        }
        __syncthreads();
        u64 BH = s_bhi, BL = s_blo;
        int si = (int)(BL & 0xFFFFull);
        bool fresh = (s_upd[si] == (u32)t);

        if (fresh) {
            if (tid == 0) {
                float4 sb = sbox[si];
                o[t * 6 + 0] = sb.x;
                o[t * 6 + 1] = sb.y;
                o[t * 6 + 2] = sb.z;
                o[t * 6 + 3] = sb.w;
                o[t * 6 + 4] = ikey((u32)(BH >> 32));
                o[t * 6 + 5] = (float)(((u32)BL) >> 16);
                selbox[t] = sb;
                s_hi[si] = 0ull;                 // kill slot
            }
            __syncthreads();
            if (tid < 32) {                       // rebuild affected chunk max
                int c = si >> 5;
                u64 hi = s_hi[c * 32 + lane];
                u64 lo = s_lo[c * 32 + lane];
                wredmax128(hi, lo);
                if (lane == 0) { s_chi[c] = hi; s_clo[c] = lo; }
            }
            t++;
        } else {
            if (tid < 32) {                       // warp 0 refreshes slot si
                int u = (int)s_upd[si];
                float4 bq = sbox[si];
                float arq = (bq.z - bq.x) * (bq.w - bq.y);
                float sc = ikey((u32)(s_hi[si] >> 32));
                for (int base = u; base < t; base += 32) {
                    int i = base + lane;
                    float d = 1.0f;
                    bool hit = false;
                    if (i < t) {
                        float4 sb = selbox[i];
                        float sar = (sb.z - sb.x) * (sb.w - sb.y);
                        float x1 = fmaxf(sb.x, bq.x);
                        float y1 = fmaxf(sb.y, bq.y);
                        float x2 = fminf(sb.z, bq.z);
                        float y2 = fminf(sb.w, bq.w);
                        float iw = fmaxf(x2 - x1, 0.0f);
                        float ih = fmaxf(y2 - y1, 0.0f);
                        float inter = iw * ih;
                        if (inter > 0.0f) {
                            float iou = __fdiv_rn(inter, ((sar + arq) - inter) + 1e-8f);
                            float t2 = iou * iou;
                            d = expf(-(t2 + t2));
                            hit = true;
                        }
                    }
                    u32 mask = __ballot_sync(0xFFFFFFFFu, hit);
                    while (mask) {                // apply in exact selection order
                        int b2 = __ffs(mask) - 1;
                        mask &= mask - 1;
                        float db = __shfl_sync(0xFFFFFFFFu, d, b2);
                        sc = sc * db;             // all lanes track identically
                    }
                }
                __syncwarp();
                if (lane == 0) {
                    s_hi[si] = (((u64)fkey(sc)) << 32) | (u32)s_hi[si];
                    s_upd[si] = (u32)t;
                }
                __syncwarp();
                int c = si >> 5;                  // rebuild affected chunk max
                u64 hi = s_hi[c * 32 + lane];
                u64 lo = s_lo[c * 32 + lane];
                wredmax128(hi, lo);
                if (lane == 0) { s_chi[c] = hi; s_clo[c] = lo; }
            }
        }
        __syncthreads();
    }
}

// ---------------- launch ----------------
extern "C" void kernel_launch(void* const* d_in, const int* in_sizes, int n_in,
                              void* d_out, int out_size) {
    const float *cls[5] = {0,0,0,0,0}, *box[5] = {0,0,0,0,0}, *anch = 0;
    for (int i = 0; i < n_in; i++) {
        const float* p = (const float*)d_in[i];
        switch (in_sizes[i]) {
            case 53084160: cls[0] = p; break;
            case 13271040: cls[1] = p; break;
            case 3317760:  cls[2] = p; break;
            case 829440:   cls[3] = p; break;
            case 207360:   cls[4] = p; break;
            case 2359296:  box[0] = p; break;
            case 589824:   box[1] = p; break;
            case 147456:   box[2] = p; break;
            case 36864:    box[3] = p; break;
            case 9216:     box[4] = p; break;
            case 196416:   anch   = p; break;
            default: break;
        }
    }
    const int NMS_SMEM = NSLOT * 16 + NSLOT * 8 + NSLOT * 8 + NSLOT * 4 + NDET * 16;
    cudaFuncSetAttribute(k_nms, cudaFuncAttributeMaxDynamicSharedMemorySize, NMS_SMEM);

    k_zero<<<64, 512>>>();
    k_sample<<<(BATCH * NS_TOTAL + 255) / 256, 256>>>(cls[0], cls[1], cls[2], cls[3], cls[4]);
    k_thresh<<<1, 32>>>();
    {
        dim3 g(542, BATCH);
        k_compact<<<g, 256>>>(cls[0], cls[1], cls[2], cls[3], cls[4]);
    }
    k_select<<<BATCH, 1024>>>(box[0], box[1], box[2], box[3], box[4], anch);
    k_nms<<<BATCH, 1024, NMS_SMEM>>>((float*)d_out);
}

// round 6
// speedup vs baseline: 5.4696x; 5.4696x over previous
#include <cuda_runtime.h>
#include <math.h>

#define BATCH 16
#define NCLS 90
#define NANCH 9
#define KSEL 5000
#define NSLOT 5120
#define NDET 100
#define CAND_CAP 131072
#define STAGE_CAP 2048
#define S_TARGET 384
#define NS_TOTAL 17264

typedef unsigned long long u64;
typedef unsigned int u32;

// ---------------- device scratch (static, no runtime alloc) ----------------
__device__ u32   g_hist[BATCH][2048];
__device__ float g_thr[BATCH];
__device__ int   g_cand_cnt[BATCH];
__device__ float g_cand_val[BATCH][CAND_CAP];
__device__ int   g_cand_idx[BATCH][CAND_CAP];

__device__ __forceinline__ u32 fkey(float f) {
    u32 u = __float_as_uint(f);
    return u ^ ((u32)((int)u >> 31) | 0x80000000u);   // monotonic: f1<f2 <=> key1<key2
}
__device__ __forceinline__ float ikey(u32 k) {
    u32 u = (k & 0x80000000u) ? (k ^ 0x80000000u) : ~k;
    return __uint_as_float(u);
}

// ---------------- kernel 0: zero counters/hist ----------------
__global__ void k_zero() {
    int t = blockIdx.x * blockDim.x + threadIdx.x;
    if (t < BATCH * 2048) ((u32*)g_hist)[t] = 0;
    if (t < BATCH) g_cand_cnt[t] = 0;
}

// ---------------- kernel 1: sampled histogram (1/64), all levels, one launch ----------------
__global__ void k_sample(const float* __restrict__ c0, const float* __restrict__ c1,
                         const float* __restrict__ c2, const float* __restrict__ c3,
                         const float* __restrict__ c4) {
    int t = blockIdx.x * blockDim.x + threadIdx.x;
    if (t >= BATCH * NS_TOTAL) return;
    int b = t / NS_TOTAL;
    int r = t - b * NS_TOTAL;
    const float* cls; int chw, i;
    if (r < 12960)      { cls = c0; chw = 3317760; i = r; }
    else if (r < 16200) { cls = c1; chw = 829440;  i = r - 12960; }
    else if (r < 17010) { cls = c2; chw = 207360;  i = r - 16200; }
    else if (r < 17213) { cls = c3; chw = 51840;   i = r - 17010; }
    else                { cls = c4; chw = 12960;   i = r - 17213; }
    int off = i * 256;
    if (off + 4 > chw) return;
    float4 v = __ldg((const float4*)(cls + (long)b * chw + off));
    atomicAdd(&g_hist[b][fkey(v.x) >> 21], 1u);
    atomicAdd(&g_hist[b][fkey(v.y) >> 21], 1u);
    atomicAdd(&g_hist[b][fkey(v.z) >> 21], 1u);
    atomicAdd(&g_hist[b][fkey(v.w) >> 21], 1u);
}

// ---------------- kernel 2: per-image threshold, warp per image ----------------
__global__ void k_thresh() {
    int w = threadIdx.x >> 5, lane = threadIdx.x & 31;
    if (w >= BATCH) return;
    const u32* h = g_hist[w];
    int base = lane * 64;
    u32 c = 0;
    #pragma unroll 8
    for (int i = 0; i < 64; i++) c += h[base + i];
    u32 s = c;
    #pragma unroll
    for (int off = 1; off < 32; off <<= 1) {
        u32 t = __shfl_down_sync(0xFFFFFFFFu, s, off);
        if (lane + off < 32) s += t;
    }
    u32 excl = s - c;                 // count in bins strictly above my 64-bin chunk
    bool cross = (excl < (u32)S_TARGET) && (excl + c >= (u32)S_TARGET);
    u32 ball = __ballot_sync(0xFFFFFFFFu, cross);
    int bin = 0;
    bool writer = cross;
    if (ball == 0) writer = (lane == 0);       // degenerate: fewer than target total
    if (writer) {
        if (cross) {
            u32 cum = excl;
            for (int i = 63; i >= 0; --i) {
                cum += h[base + i];
                if (cum >= (u32)S_TARGET) { bin = base + i; break; }
            }
        }
        u32 kthr = ((u32)bin) << 21;
        u32 u = (kthr & 0x80000000u) ? (kthr ^ 0x80000000u) : ~kthr;
        g_thr[w] = __uint_as_float(u);
    }
}

// ---------------- kernel 3: full scan + compaction, all levels, one launch ----------------
__global__ void __launch_bounds__(256, 6) k_compact(
        const float* __restrict__ c0, const float* __restrict__ c1,
        const float* __restrict__ c2, const float* __restrict__ c3,
        const float* __restrict__ c4) {
    __shared__ float s_val[STAGE_CAP];
    __shared__ int   s_idx[STAGE_CAP];
    __shared__ int   s_cnt, s_base;
    int b = blockIdx.y;
    int tid = threadIdx.x;
    int blk = blockIdx.x;
    const float* cls; int chw4, shHW, aoff, lb;
    if (blk < 405)      { cls = c0; chw4 = 829440; shHW = 12; aoff = 0;     lb = blk; }
    else if (blk < 507) { cls = c1; chw4 = 207360; shHW = 10; aoff = 36864; lb = blk - 405; }
    else if (blk < 533) { cls = c2; chw4 = 51840;  shHW = 8;  aoff = 46080; lb = blk - 507; }
    else if (blk < 540) { cls = c3; chw4 = 12960;  shHW = 6;  aoff = 48384; lb = blk - 533; }
    else                { cls = c4; chw4 = 3240;   shHW = 4;  aoff = 48960; lb = blk - 540; }

    if (tid == 0) s_cnt = 0;
    __syncthreads();
    float thr = g_thr[b];
    const float4* base = (const float4*)cls + (long)b * chw4;
    int i0 = lb * 2048 + tid;

    float4 v[8];
    #pragma unroll
    for (int g = 0; g < 8; g++) {
        int i4 = i0 + g * 256;
        v[g] = (i4 < chw4) ? __ldg(base + i4)
                           : make_float4(-INFINITY, -INFINITY, -INFINITY, -INFINITY);
    }
    #pragma unroll
    for (int g = 0; g < 8; g++) {
        int i4 = i0 + g * 256;
        #pragma unroll
        for (int j = 0; j < 4; j++) {
            float f = (j == 0) ? v[g].x : (j == 1) ? v[g].y : (j == 2) ? v[g].z : v[g].w;
            if (f >= thr) {
                int lin = i4 * 4 + j;
                int ch = lin >> shHW;                 // 0..809 (= a*90 + c)
                int pix = lin & ((1 << shHW) - 1);    // h*W + w
                int a = ch / NCLS;
                int c = ch - a * NCLS;
                int flat = (aoff + pix * NANCH + a) * NCLS + c;
                int p = atomicAdd(&s_cnt, 1);
                if (p < STAGE_CAP) { s_val[p] = f; s_idx[p] = flat; }
            }
        }
    }
    __syncthreads();
    if (tid == 0) {
        int n = min(s_cnt, STAGE_CAP);
        s_base = atomicAdd(&g_cand_cnt[b], n);
        s_cnt = n;
    }
    __syncthreads();
    for (int i = tid; i < s_cnt; i += 256) {
        int gi = s_base + i;
        if (gi < CAND_CAP) {
            g_cand_val[b][gi] = s_val[i];
            g_cand_idx[b][gi] = s_idx[i];
        }
    }
}

// ---------------- fused kernel 4: top-K select + decode + eager soft-NMS ----------------
// dynamic smem layout (bytes):
//   [0)        sbox   float4[NSLOT]   81920
//   [81920)    s_sc   float [NSLOT]   20480
//   [102400)   s_org  u32   [NSLOT]   20480
//   [122880)   s_fid  u32   [NSLOT]   20480
//   [143360)   s_cls  u32   [NSLOT]   20480
//   [163840)   transient select arrays:
//              hist u32[4096] 16384 | part u32[1024] 4096 |
//              tkey u32[1024] 4096 | tidx u32[1024] 4096 | tsel u8[1024] 1024
// total 193536
#define POST_SMEM 193536
extern __shared__ unsigned char post_dyn[];

struct DecodeTargets {
    float4* sbox; float* s_sc; u32* s_org; u32* s_fid; u32* s_cls;
};

__device__ __forceinline__ void decode_store(
    const DecodeTargets& T, int b, int slot, float v, int flat,
    const float* __restrict__ b0, const float* __restrict__ b1,
    const float* __restrict__ b2, const float* __restrict__ b3,
    const float* __restrict__ b4, const float* __restrict__ anchors)
{
    int anchor = flat / NCLS;
    int cls = flat - anchor * NCLS;

    const float* bp; int hw, loc;
    if (anchor < 36864)      { bp = b0; hw = 4096; loc = anchor; }
    else if (anchor < 46080) { bp = b1; hw = 1024; loc = anchor - 36864; }
    else if (anchor < 48384) { bp = b2; hw = 256;  loc = anchor - 46080; }
    else if (anchor < 48960) { bp = b3; hw = 64;   loc = anchor - 48384; }
    else                     { bp = b4; hw = 16;   loc = anchor - 48960; }
    int a = loc % NANCH;
    int pix = loc / NANCH;

    const float* q = bp + ((long)b * 36 + a * 4) * hw + pix;
    float ty = __ldg(q);
    float tx = __ldg(q + hw);
    float th = __ldg(q + 2 * hw);
    float tw = __ldg(q + 3 * hw);

    float4 anc = __ldg((const float4*)(anchors + 4 * anchor)); // y1,x1,y2,x2
    float ya = (anc.x + anc.z) * 0.5f;
    float xa = (anc.y + anc.w) * 0.5f;
    float ha = anc.z - anc.x;
    float wa = anc.w - anc.y;
    float w = expf(tw) * wa;
    float h = expf(th) * ha;
    float yc = ty * ha + ya;
    float xc = tx * wa + xa;

    T.sbox[slot] = make_float4(xc - w * 0.5f, yc - h * 0.5f,
                               xc + w * 0.5f, yc + h * 0.5f);
    T.s_sc[slot] = __fdiv_rn(1.0f, 1.0f + expf(-v));
    T.s_cls[slot] = (u32)cls;
    T.s_org[slot] = fkey(v);
    T.s_fid[slot] = (u32)flat;
}

__global__ void __launch_bounds__(1024, 1) k_post(
    const float* __restrict__ b0, const float* __restrict__ b1,
    const float* __restrict__ b2, const float* __restrict__ b3,
    const float* __restrict__ b4, const float* __restrict__ anchors,
    float* __restrict__ out)
{
    DecodeTargets T;
    T.sbox  = (float4*)(post_dyn);
    T.s_sc  = (float*)(post_dyn + 81920);
    T.s_org = (u32*)(post_dyn + 102400);
    T.s_fid = (u32*)(post_dyn + 122880);
    T.s_cls = (u32*)(post_dyn + 143360);
    u32* hist = (u32*)(post_dyn + 163840);
    u32* s_part = (u32*)(post_dyn + 163840 + 16384);
    u32* s_tie_key = (u32*)(post_dyn + 163840 + 20480);
    int* s_tie_idx = (int*)(post_dyn + 163840 + 24576);
    unsigned char* s_tie_sel = (unsigned char*)(post_dyn + 163840 + 28672);

    __shared__ int sb_bin, sb_above;
    __shared__ int s_tie_cnt, s_out_cnt;

    int b = blockIdx.x;
    int tid = threadIdx.x;
    int m = min(g_cand_cnt[b], CAND_CAP);

    // ======== PHASE A: exact top-K selection (radix on monotone key) ========
    for (int i = tid; i < 4096; i += 1024) hist[i] = 0;
    if (tid == 0) { s_tie_cnt = 0; s_out_cnt = 0; sb_bin = -1; }
    __syncthreads();
    for (int i = tid; i < m; i += 1024)
        atomicAdd(&hist[fkey(g_cand_val[b][i]) >> 20], 1u);
    __syncthreads();

    // parallel suffix-sum bin search: largest bin with suffix(bin) >= KSEL
    {
        u32 loc = hist[4 * tid] + hist[4 * tid + 1] + hist[4 * tid + 2] + hist[4 * tid + 3];
        s_part[tid] = loc;
        __syncthreads();
        for (int off = 1; off < 1024; off <<= 1) {
            u32 v = s_part[tid];
            u32 add = (tid + off < 1024) ? s_part[tid + off] : 0;
            __syncthreads();
            s_part[tid] = v + add;
            __syncthreads();
        }
        u32 running = (tid < 1023) ? s_part[tid + 1] : 0;
        #pragma unroll
        for (int bb = 3; bb >= 0; --bb) {
            u32 c = hist[4 * tid + bb];
            if (running < (u32)KSEL && running + c >= (u32)KSEL) {
                sb_bin = 4 * tid + bb;
                sb_above = (int)running;
            }
            running += c;
        }
    }
    __syncthreads();
    if (tid == 0 && sb_bin < 0) { sb_bin = 0; sb_above = (int)s_part[0]; }
    __syncthreads();
    int B1 = sb_bin;
    int cntAbove = sb_above;
    __syncthreads();

    // round 2: next 12 bits within bin B1
    for (int i = tid; i < 4096; i += 1024) hist[i] = 0;
    if (tid == 0) sb_bin = -1;
    __syncthreads();
    for (int i = tid; i < m; i += 1024) {
        u32 k = fkey(g_cand_val[b][i]);
        if ((int)(k >> 20) == B1) atomicAdd(&hist[(k >> 8) & 0xFFF], 1u);
    }
    __syncthreads();
    int K2 = KSEL - cntAbove;
    {
        u32 loc = hist[4 * tid] + hist[4 * tid + 1] + hist[4 * tid + 2] + hist[4 * tid + 3];
        s_part[tid] = loc;
        __syncthreads();
        for (int off = 1; off < 1024; off <<= 1) {
            u32 v = s_part[tid];
            u32 add = (tid + off < 1024) ? s_part[tid + off] : 0;
            __syncthreads();
            s_part[tid] = v + add;
            __syncthreads();
        }
        u32 running = (tid < 1023) ? s_part[tid + 1] : 0;
        #pragma unroll
        for (int bb = 3; bb >= 0; --bb) {
            u32 c = hist[4 * tid + bb];
            if (running < (u32)K2 && running + c >= (u32)K2) {
                sb_bin = 4 * tid + bb;
                sb_above = (int)running;
            }
            running += c;
        }
    }
    __syncthreads();
    if (tid == 0 && sb_bin < 0) { sb_bin = 0; sb_above = 0; }
    __syncthreads();
    u32 P = (((u32)B1) << 12) | (u32)sb_bin;
    int need2 = K2 - sb_above;
    __syncthreads();

    // round 3: exact ranking of tie bucket (value desc, flat idx asc)
    for (int i = tid; i < m; i += 1024) {
        u32 k = fkey(g_cand_val[b][i]);
        if ((k >> 8) == P) {
            int p = atomicAdd(&s_tie_cnt, 1);
            if (p < 1024) { s_tie_key[p] = k; s_tie_idx[p] = g_cand_idx[b][i]; }
        }
    }
    __syncthreads();
    int ne = min(s_tie_cnt, 1024);
    for (int j = tid; j < ne; j += 1024) {
        u32 kj = s_tie_key[j]; int ij = s_tie_idx[j]; int r = 0;
        for (int i = 0; i < ne; i++) {
            u32 ki = s_tie_key[i];
            if (ki > kj || (ki == kj && s_tie_idx[i] < ij)) r++;
        }
        s_tie_sel[j] = (r < need2) ? 1 : 0;
    }
    __syncthreads();

    // emit exact top-K (unordered) with fused decode into SHARED slot arrays
    for (int i = tid; i < m; i += 1024) {
        float v = g_cand_val[b][i];
        u32 k = fkey(v);
        if ((k >> 8) > P) {
            int p = atomicAdd(&s_out_cnt, 1);
            if (p < KSEL) decode_store(T, b, p, v, g_cand_idx[b][i], b0, b1, b2, b3, b4, anchors);
        }
    }
    __syncthreads();
    for (int j = tid; j < ne; j += 1024) {
        if (s_tie_sel[j]) {
            int p = atomicAdd(&s_out_cnt, 1);
            if (p < KSEL) decode_store(T, b, p, ikey(s_tie_key[j]), s_tie_idx[j], b0, b1, b2, b3, b4, anchors);
        }
    }
    __syncthreads();
    int cnt = min(s_out_cnt, KSEL);
    for (int k = cnt + tid; k < NSLOT; k += 1024) {
        T.sbox[k] = make_float4(0.f, 0.f, 0.f, 0.f);
        T.s_sc[k] = -INFINITY;
        T.s_cls[k] = 0;
        T.s_org[k] = 0u;
        T.s_fid[k] = 0xFFFFFFFFu;
    }
    __syncthreads();

    // ======== PHASE B: eager gaussian soft-NMS (proven R4 structure) ========
    float4* sbox = T.sbox;
    float sc[5], ar[5];
    u32 org[5];
    u64 lo[5];
    #pragma unroll
    for (int q = 0; q < 5; q++) {
        int s = q * 1024 + tid;
        float4 v = sbox[s];
        sc[q] = T.s_sc[s];
        org[q] = T.s_org[s];
        u32 fidx = T.s_fid[s];
        lo[q] = (((u64)(~fidx)) << 32) | (u32)s;
        ar[q] = (v.z - v.x) * (v.w - v.y);
    }
    __shared__ u64 s_whi[32], s_wlo[32];
    __shared__ u64 s_bhi, s_blo;
    float* o = out + b * (NDET * 6);
    __syncthreads();

    for (int it = 0; it < NDET; it++) {
        // argmax with 128-bit comparator: (curr score desc, orig logit desc, flat idx asc)
        u64 bhi = 0ull, blo = 0ull;
        #pragma unroll
        for (int q = 0; q < 5; q++) {
            u64 hi = (((u64)fkey(sc[q])) << 32) | org[q];
            if (hi > bhi || (hi == bhi && lo[q] > blo)) { bhi = hi; blo = lo[q]; }
        }
        #pragma unroll
        for (int off = 16; off > 0; off >>= 1) {
            u64 ohi = __shfl_xor_sync(0xFFFFFFFFu, bhi, off);
            u64 olo = __shfl_xor_sync(0xFFFFFFFFu, blo, off);
            if (ohi > bhi || (ohi == bhi && olo > blo)) { bhi = ohi; blo = olo; }
        }
        if ((tid & 31) == 0) { s_whi[tid >> 5] = bhi; s_wlo[tid >> 5] = blo; }
        __syncthreads();
        if (tid < 32) {
            bhi = s_whi[tid]; blo = s_wlo[tid];
            #pragma unroll
            for (int off = 16; off > 0; off >>= 1) {
                u64 ohi = __shfl_xor_sync(0xFFFFFFFFu, bhi, off);
                u64 olo = __shfl_xor_sync(0xFFFFFFFFu, blo, off);
                if (ohi > bhi || (ohi == bhi && olo > blo)) { bhi = ohi; blo = olo; }
            }
            if (tid == 0) { s_bhi = bhi; s_blo = blo; }
        }
        __syncthreads();
        u64 BH = s_bhi, BL = s_blo;
        int si = (int)(BL & 0xFFFFFFFFull);
        float ssel = ikey((u32)(BH >> 32));
        float4 sb = sbox[si];
        float sar = (sb.z - sb.x) * (sb.w - sb.y);

        if ((si & 1023) == tid) {            // owner emits detection row + kills slot
            o[it * 6 + 0] = sb.x;
            o[it * 6 + 1] = sb.y;
            o[it * 6 + 2] = sb.z;
            o[it * 6 + 3] = sb.w;
            o[it * 6 + 4] = ssel;
            o[it * 6 + 5] = (float)T.s_cls[si];
            sc[si >> 10] = -INFINITY;
        }
        // decay
        #pragma unroll
        for (int q = 0; q < 5; q++) {
            float4 bq = sbox[q * 1024 + tid];
            float x1 = fmaxf(sb.x, bq.x);
            float y1 = fmaxf(sb.y, bq.y);
            float x2 = fminf(sb.z, bq.z);
            float y2 = fminf(sb.w, bq.w);
            float iw = fmaxf(x2 - x1, 0.0f);
            float ih = fmaxf(y2 - y1, 0.0f);
            float inter = iw * ih;
            if (inter > 0.0f) {
                float iou = __fdiv_rn(inter, ((sar + ar[q]) - inter) + 1e-8f);
                float t2 = iou * iou;
                sc[q] *= expf(-(t2 + t2));   // exp(-(iou^2)/0.5), /0.5 is exact *2
            }
        }
    }
}

// ---------------- launch ----------------
extern "C" void kernel_launch(void* const* d_in, const int* in_sizes, int n_in,
                              void* d_out, int out_size) {
    const float *cls[5] = {0,0,0,0,0}, *box[5] = {0,0,0,0,0}, *anch = 0;
    for (int i = 0; i < n_in; i++) {
        const float* p = (const float*)d_in[i];
        switch (in_sizes[i]) {
            case 53084160: cls[0] = p; break;
            case 13271040: cls[1] = p; break;
            case 3317760:  cls[2] = p; break;
            case 829440:   cls[3] = p; break;
            case 207360:   cls[4] = p; break;
            case 2359296:  box[0] = p; break;
            case 589824:   box[1] = p; break;
            case 147456:   box[2] = p; break;
            case 36864:    box[3] = p; break;
            case 9216:     box[4] = p; break;
            case 196416:   anch   = p; break;
            default: break;
        }
    }
    cudaFuncSetAttribute(k_post, cudaFuncAttributeMaxDynamicSharedMemorySize, POST_SMEM);

    k_zero<<<64, 512>>>();
    k_sample<<<(BATCH * NS_TOTAL + 255) / 256, 256>>>(cls[0], cls[1], cls[2], cls[3], cls[4]);
    k_thresh<<<1, 512>>>();
    {
        dim3 g(542, BATCH);
        k_compact<<<g, 256>>>(cls[0], cls[1], cls[2], cls[3], cls[4]);
    }
    k_post<<<BATCH, 1024, POST_SMEM>>>(box[0], box[1], box[2], box[3], box[4], anch, (float*)d_out);
}